// round 1
// baseline (speedup 1.0000x reference)
#include <cuda_runtime.h>
#include <cstdint>

#define E_   12
#define D_   768
#define KDIM 1536          // 2*D
#define NE   24            // 12 audio + 12 image experts
#define ROWS 64            // batch rows per CTA
#define KC   64            // K chunk
#define GSTR (KC + 4)      // padded row stride (floats) for bank-conflict-free LDS

__device__ __forceinline__ void ffma2(unsigned long long &d,
                                      unsigned long long a,
                                      unsigned long long b) {
    // Blackwell packed f32x2 FMA: two FMAs per instruction
    asm("fma.rn.f32x2 %0, %1, %2, %0;" : "+l"(d) : "l"(a), "l"(b));
}

__device__ __forceinline__ float2 unpack2(unsigned long long v) {
    float2 r;
    asm("mov.b64 {%0, %1}, %2;" : "=f"(r.x), "=f"(r.y) : "l"(v));
    return r;
}

__global__ void gate_fused_kernel(
    const float* __restrict__ audio, const float* __restrict__ image,
    const float* __restrict__ Wa,    const float* __restrict__ ba,
    const float* __restrict__ Wi,    const float* __restrict__ bi,
    const float* __restrict__ ga,    const float* __restrict__ gi,
    float* __restrict__ out, int B)
{
    __shared__ float Gs[ROWS][GSTR];   // gate-input tile
    __shared__ float Ws[NE][GSTR];     // weight tile (both gates stacked)
    __shared__ float Ls[ROWS][NE];     // logits
    __shared__ float scl[2][ROWS];     // ret[argmax]/12 per gate
    __shared__ int   sidx[2][ROWS];    // argmax per gate

    const int tid  = threadIdx.x;
    const int row0 = blockIdx.x * ROWS;
    const int warp = tid >> 5;
    const int lane = tid & 31;
    const int eg   = lane & 7;         // expert group: experts 3eg..3eg+2
    const int rg   = lane >> 3;        // row group within warp
    const int lr0  = warp * 8 + rg * 2;  // local rows lr0, lr0+1

    unsigned long long acc[6];
    #pragma unroll
    for (int i = 0; i < 6; i++) acc[i] = 0ULL;

    const size_t rowstride = (size_t)E_ * D_;  // 9216

    for (int kc = 0; kc < KDIM; kc += KC) {
        const bool fromA  = (kc < D_);
        const float* src  = fromA ? audio : image;
        const int   kbase = fromA ? kc : (kc - D_);

        // Stage gate tile: 64 rows x 16 float4 = 1024 float4, 4 per thread
        #pragma unroll
        for (int it = 0; it < (ROWS * (KC / 4)) / 256; it++) {
            int i = tid + it * 256;
            int r = i >> 4;
            int c = i & 15;
            int b = row0 + r;
            if (b >= B) b = B - 1;     // clamp (safe duplicate read)
            float4 v = *(const float4*)(src + (size_t)b * rowstride + kbase + c * 4);
            *(float4*)&Gs[r][c * 4] = v;
        }
        // Stage W tile: 24 x 16 float4 = 384 float4
        for (int i = tid; i < NE * (KC / 4); i += 256) {
            int e = i >> 4;
            int c = i & 15;
            const float* wsrc = (e < E_) ? (Wa + (size_t)e * KDIM)
                                         : (Wi + (size_t)(e - E_) * KDIM);
            float4 v = *(const float4*)(wsrc + kc + c * 4);
            *(float4*)&Ws[e][c * 4] = v;
        }
        __syncthreads();

        #pragma unroll
        for (int kk = 0; kk < KC; kk += 4) {
            ulonglong2 g0 = *(const ulonglong2*)&Gs[lr0][kk];
            ulonglong2 g1 = *(const ulonglong2*)&Gs[lr0 + 1][kk];
            ulonglong2 w0 = *(const ulonglong2*)&Ws[3 * eg + 0][kk];
            ulonglong2 w1 = *(const ulonglong2*)&Ws[3 * eg + 1][kk];
            ulonglong2 w2 = *(const ulonglong2*)&Ws[3 * eg + 2][kk];
            ffma2(acc[0], g0.x, w0.x); ffma2(acc[0], g0.y, w0.y);
            ffma2(acc[1], g0.x, w1.x); ffma2(acc[1], g0.y, w1.y);
            ffma2(acc[2], g0.x, w2.x); ffma2(acc[2], g0.y, w2.y);
            ffma2(acc[3], g1.x, w0.x); ffma2(acc[3], g1.y, w0.y);
            ffma2(acc[4], g1.x, w1.x); ffma2(acc[4], g1.y, w1.y);
            ffma2(acc[5], g1.x, w2.x); ffma2(acc[5], g1.y, w2.y);
        }
        __syncthreads();
    }

    // Deposit logits
    #pragma unroll
    for (int j = 0; j < 2; j++) {
        #pragma unroll
        for (int m = 0; m < 3; m++) {
            float2 p = unpack2(acc[j * 3 + m]);
            Ls[lr0 + j][3 * eg + m] = p.x + p.y;
        }
    }
    __syncthreads();

    // Gumbel-softmax straight-through per row (one thread per row)
    if (tid < ROWS) {
        int b = row0 + tid;
        if (b < B) {
            float* retA = out + (size_t)B * KDIM;
            float* retI = retA + (size_t)B * E_;
            #pragma unroll
            for (int gsel = 0; gsel < 2; gsel++) {
                const float* bias = gsel ? bi : ba;
                const float* gum  = gsel ? gi : ga;
                float* retp       = gsel ? retI : retA;
                float l[E_];
                float mx = -1e30f;
                #pragma unroll
                for (int e = 0; e < E_; e++) {
                    l[e] = Ls[tid][gsel * E_ + e] + bias[e] + gum[(size_t)b * E_ + e];
                    mx = fmaxf(mx, l[e]);
                }
                float s = 0.f;
                float y[E_];
                #pragma unroll
                for (int e = 0; e < E_; e++) { y[e] = expf(l[e] - mx); s += y[e]; }
                const float inv = 1.0f / s;
                float ys[E_];
                int   am = 0;
                float best = y[0] * inv;
                ys[0] = best;
                #pragma unroll
                for (int e = 1; e < E_; e++) {
                    ys[e] = y[e] * inv;
                    if (ys[e] > best) { best = ys[e]; am = e; }  // first-max like jnp.argmax
                }
                #pragma unroll
                for (int e = 0; e < E_; e++) {
                    float h = (e == am) ? 1.0f : 0.0f;
                    retp[(size_t)b * E_ + e] = (h - ys[e]) + ys[e];  // exact ref arithmetic
                }
                scl[gsel][tid]  = ((1.0f - ys[am]) + ys[am]) * (1.0f / 12.0f);
                sidx[gsel][tid] = am;
            }
        }
    }
    __syncthreads();

    // Gather selected expert row, scale, write output: ROWS * 384 float4
    const int V4 = KDIM / 4;  // 384
    for (int i = tid; i < ROWS * V4; i += 256) {
        int r = i / V4;
        int c = i - r * V4;
        int b = row0 + r;
        if (b >= B) break;    // r is nondecreasing in i
        float4 v;
        float  s;
        if (c < (D_ / 4)) {
            v = *(const float4*)(audio + ((size_t)b * E_ + sidx[0][r]) * D_ + c * 4);
            s = scl[0][r];
        } else {
            v = *(const float4*)(image + ((size_t)b * E_ + sidx[1][r]) * D_ + (c - D_ / 4) * 4);
            s = scl[1][r];
        }
        v.x *= s; v.y *= s; v.z *= s; v.w *= s;
        *(float4*)(out + (size_t)b * KDIM + c * 4) = v;
    }
}

extern "C" void kernel_launch(void* const* d_in, const int* in_sizes, int n_in,
                              void* d_out, int out_size) {
    const float* audio = (const float*)d_in[0];
    const float* image = (const float*)d_in[1];
    const float* Wa    = (const float*)d_in[2];
    const float* ba    = (const float*)d_in[3];
    const float* Wi    = (const float*)d_in[4];
    const float* bi    = (const float*)d_in[5];
    const float* ga    = (const float*)d_in[6];
    const float* gi    = (const float*)d_in[7];
    float* out = (float*)d_out;

    const int B = in_sizes[0] / (E_ * D_);   // 16384
    const int grid = (B + ROWS - 1) / ROWS;  // 256

    gate_fused_kernel<<<grid, 256>>>(audio, image, Wa, ba, Wi, bi, ga, gi, out, B);
}

// round 2
// speedup vs baseline: 1.0401x; 1.0401x over previous
#include <cuda_runtime.h>
#include <cstdint>

#define E_   12
#define D_   768
#define KDIM 1536           // 2*D
#define NE   24             // 12 audio + 12 image experts
#define ROWS 32             // batch rows per CTA (kernel 1)
#define KC   128            // K chunk
#define GSTR (KC + 4)       // padded row stride (floats), conflict-free LDS
#define BMAX 16384
#define R2   8              // rows per CTA (kernel 2)

// Scratch for cross-kernel handoff (static device arrays — allocation-free)
__device__ float g_scl[2 * BMAX];
__device__ int   g_idx[2 * BMAX];

__device__ __forceinline__ void ffma2(unsigned long long &d,
                                      unsigned long long a,
                                      unsigned long long b) {
    asm("fma.rn.f32x2 %0, %1, %2, %0;" : "+l"(d) : "l"(a), "l"(b));
}

__device__ __forceinline__ float2 unpack2(unsigned long long v) {
    float2 r;
    asm("mov.b64 {%0, %1}, %2;" : "=f"(r.x), "=f"(r.y) : "l"(v));
    return r;
}

// ───────────── Kernel 1: logits GEMM + gumbel-softmax-ST + ret writes ─────────────
__global__ void __launch_bounds__(256, 4) gate_logits_kernel(
    const float* __restrict__ audio, const float* __restrict__ image,
    const float* __restrict__ Wa,    const float* __restrict__ ba,
    const float* __restrict__ Wi,    const float* __restrict__ bi,
    const float* __restrict__ ga,    const float* __restrict__ gi,
    float* __restrict__ out, int B)
{
    __shared__ float Gs[ROWS][GSTR];
    __shared__ float Ws[NE][GSTR];
    __shared__ float Ls[ROWS][NE];

    const int tid  = threadIdx.x;
    const int row0 = blockIdx.x * ROWS;
    const int warp = tid >> 5;
    const int lane = tid & 31;
    const int eg   = lane & 7;          // experts 3eg..3eg+2
    const int rg   = lane >> 3;         // row within warp's 4-row group
    const int lrow = warp * 4 + rg;     // local row (0..31)

    unsigned long long acc[3];
    #pragma unroll
    for (int i = 0; i < 3; i++) acc[i] = 0ULL;

    const size_t rowstride = (size_t)E_ * D_;  // 9216

    for (int kc = 0; kc < KDIM; kc += KC) {
        const bool fromA  = (kc < D_);
        const float* src  = fromA ? audio : image;
        const int   kbase = fromA ? kc : (kc - D_);

        // Stage gate tile: ROWS x 32 float4 = 1024 float4, 4/thread
        #pragma unroll
        for (int it = 0; it < (ROWS * (KC / 4)) / 256; it++) {
            int i = tid + it * 256;
            int r = i >> 5;
            int c = i & 31;
            int b = row0 + r;
            if (b >= B) b = B - 1;
            float4 v = *(const float4*)(src + (size_t)b * rowstride + kbase + c * 4);
            *(float4*)&Gs[r][c * 4] = v;
        }
        // Stage W tile: 24 x 32 float4 = 768 float4, 3/thread
        for (int i = tid; i < NE * (KC / 4); i += 256) {
            int e = i >> 5;
            int c = i & 31;
            const float* wsrc = (e < E_) ? (Wa + (size_t)e * KDIM)
                                         : (Wi + (size_t)(e - E_) * KDIM);
            float4 v = *(const float4*)(wsrc + kc + c * 4);
            *(float4*)&Ws[e][c * 4] = v;
        }
        __syncthreads();

        #pragma unroll
        for (int kk = 0; kk < KC; kk += 4) {
            ulonglong2 g  = *(const ulonglong2*)&Gs[lrow][kk];
            ulonglong2 w0 = *(const ulonglong2*)&Ws[3 * eg + 0][kk];
            ulonglong2 w1 = *(const ulonglong2*)&Ws[3 * eg + 1][kk];
            ulonglong2 w2 = *(const ulonglong2*)&Ws[3 * eg + 2][kk];
            ffma2(acc[0], g.x, w0.x); ffma2(acc[0], g.y, w0.y);
            ffma2(acc[1], g.x, w1.x); ffma2(acc[1], g.y, w1.y);
            ffma2(acc[2], g.x, w2.x); ffma2(acc[2], g.y, w2.y);
        }
        __syncthreads();
    }

    // Deposit logits
    #pragma unroll
    for (int m = 0; m < 3; m++) {
        float2 p = unpack2(acc[m]);
        Ls[lrow][3 * eg + m] = p.x + p.y;
    }
    __syncthreads();

    // Gumbel-softmax straight-through per row (one thread per row)
    if (tid < ROWS) {
        int b = row0 + tid;
        if (b < B) {
            float* retA = out + (size_t)B * KDIM;
            float* retI = retA + (size_t)B * E_;
            #pragma unroll
            for (int gsel = 0; gsel < 2; gsel++) {
                const float* bias = gsel ? bi : ba;
                const float* gum  = gsel ? gi : ga;
                float* retp       = gsel ? retI : retA;
                float l[E_];
                float mx = -1e30f;
                #pragma unroll
                for (int e = 0; e < E_; e++) {
                    l[e] = Ls[tid][gsel * E_ + e] + bias[e] + gum[(size_t)b * E_ + e];
                    mx = fmaxf(mx, l[e]);
                }
                float s = 0.f;
                float y[E_];
                #pragma unroll
                for (int e = 0; e < E_; e++) { y[e] = expf(l[e] - mx); s += y[e]; }
                const float inv = 1.0f / s;
                float ys[E_];
                int   am = 0;
                float best = y[0] * inv;
                ys[0] = best;
                #pragma unroll
                for (int e = 1; e < E_; e++) {
                    ys[e] = y[e] * inv;
                    if (ys[e] > best) { best = ys[e]; am = e; }  // first-max (jnp.argmax)
                }
                #pragma unroll
                for (int e = 0; e < E_; e++) {
                    float h = (e == am) ? 1.0f : 0.0f;
                    retp[(size_t)b * E_ + e] = (h - ys[e]) + ys[e];  // exact ref arithmetic
                }
                g_scl[gsel * BMAX + b] = ((1.0f - ys[am]) + ys[am]) * (1.0f / 12.0f);
                g_idx[gsel * BMAX + b] = am;
            }
        }
    }
}

// ───────────── Kernel 2: gather selected expert rows, scale, store ─────────────
__global__ void __launch_bounds__(256) gate_gather_kernel(
    const float* __restrict__ audio, const float* __restrict__ image,
    float* __restrict__ out, int B)
{
    __shared__ float s_scl[2][R2];
    __shared__ int   s_idx[2][R2];

    const int tid  = threadIdx.x;
    const int row0 = blockIdx.x * R2;

    if (tid < 2 * R2) {
        int gsel = tid >> 3;       // R2 == 8
        int r    = tid & 7;
        int b    = row0 + r;
        if (b < B) {
            s_scl[gsel][r] = g_scl[gsel * BMAX + b];
            s_idx[gsel][r] = g_idx[gsel * BMAX + b];
        }
    }
    __syncthreads();

    const int V4 = KDIM / 4;  // 384 float4 per row
    #pragma unroll
    for (int j = 0; j < (R2 * V4) / 256; j++) {   // 12 iterations
        int i = tid + j * 256;
        int r = i / V4;
        int c = i - r * V4;
        int b = row0 + r;
        if (b >= B) continue;
        float4 v;
        float  s;
        if (c < (D_ / 4)) {
            v = *(const float4*)(audio + ((size_t)b * E_ + s_idx[0][r]) * D_ + c * 4);
            s = s_scl[0][r];
        } else {
            v = *(const float4*)(image + ((size_t)b * E_ + s_idx[1][r]) * D_ + (c - D_ / 4) * 4);
            s = s_scl[1][r];
        }
        v.x *= s; v.y *= s; v.z *= s; v.w *= s;
        *(float4*)(out + (size_t)b * KDIM + c * 4) = v;
    }
}

extern "C" void kernel_launch(void* const* d_in, const int* in_sizes, int n_in,
                              void* d_out, int out_size) {
    const float* audio = (const float*)d_in[0];
    const float* image = (const float*)d_in[1];
    const float* Wa    = (const float*)d_in[2];
    const float* ba    = (const float*)d_in[3];
    const float* Wi    = (const float*)d_in[4];
    const float* bi    = (const float*)d_in[5];
    const float* ga    = (const float*)d_in[6];
    const float* gi    = (const float*)d_in[7];
    float* out = (float*)d_out;

    const int B = in_sizes[0] / (E_ * D_);   // 16384

    const int grid1 = (B + ROWS - 1) / ROWS;  // 512
    gate_logits_kernel<<<grid1, 256>>>(audio, image, Wa, ba, Wi, bi, ga, gi, out, B);

    const int grid2 = (B + R2 - 1) / R2;      // 2048
    gate_gather_kernel<<<grid2, 256>>>(audio, image, out, B);
}

// round 3
// speedup vs baseline: 1.3360x; 1.2846x over previous
#include <cuda_runtime.h>
#include <cstdint>

#define E_    12
#define D_    768
#define KDIM  1536
#define NE    24
#define ROWS  32            // batch rows per CTA (kernel 1)
#define KC    128           // K chunk
#define NCH   (KDIM / KC)   // 12
#define GSTR  132           // row stride (floats): 528 B == 16 mod 128 -> conflict-free
#define BMAX  16384
#define R2    8             // rows per CTA (kernel 2)

// Cross-kernel handoff (static device arrays — allocation-free)
__device__ float g_scl[2 * BMAX];
__device__ int   g_idx[2 * BMAX];

__device__ __forceinline__ void ffma2(unsigned long long &d,
                                      unsigned long long a,
                                      unsigned long long b) {
    asm("fma.rn.f32x2 %0, %1, %2, %0;" : "+l"(d) : "l"(a), "l"(b));
}

__device__ __forceinline__ float2 unpack2(unsigned long long v) {
    float2 r;
    asm("mov.b64 {%0, %1}, %2;" : "=f"(r.x), "=f"(r.y) : "l"(v));
    return r;
}

// ───────── Kernel 1: logits GEMM (reg-tiled, split-K) + gumbel-softmax-ST ─────────
__global__ void __launch_bounds__(256, 3) gate_logits_kernel(
    const float* __restrict__ audio, const float* __restrict__ image,
    const float* __restrict__ Wa,    const float* __restrict__ ba,
    const float* __restrict__ Wi,    const float* __restrict__ bi,
    const float* __restrict__ ga,    const float* __restrict__ gi,
    float* __restrict__ out, int B)
{
    __shared__ union {
        struct { float G[ROWS][GSTR]; float W[NE][GSTR]; } t;  // 29.6 KB
        float Lp[8][ROWS][NE];                                  // 24.6 KB (split-K partials)
    } S;
    __shared__ float Ls[ROWS][NE];

    const int tid  = threadIdx.x;
    const int row0 = blockIdx.x * ROWS;
    const int ks   = tid >> 5;        // warp = K-slice (8 slices x 192 floats)
    const int rg   = (tid >> 2) & 7;  // rows rg, rg+8, rg+16, rg+24
    const int eg   = tid & 3;         // experts eg, eg+4, ..., eg+20

    unsigned long long acc[6][4];
    #pragma unroll
    for (int m = 0; m < 6; m++)
        #pragma unroll
        for (int i = 0; i < 4; i++) acc[m][i] = 0ULL;

    const size_t rowstride = (size_t)E_ * D_;  // 9216

    for (int c = 0; c < NCH; c++) {
        const int kc      = c * KC;
        const bool fromA  = (kc < D_);
        const float* src  = fromA ? audio : image;
        const int   kbase = fromA ? kc : (kc - D_);

        // Stage G tile: 32 rows x 32 quads, 4 quads/thread, coalesced LDG.128
        {
            int r = tid >> 3;
            int b = row0 + r; if (b >= B) b = B - 1;
            const float* rp = src + (size_t)b * rowstride + kbase;
            int q0 = tid & 7;
            #pragma unroll
            for (int it = 0; it < 4; it++) {
                int q = q0 + 8 * it;
                *(float4*)&S.t.G[r][q * 4] = *(const float4*)(rp + q * 4);
            }
        }
        // Stage W tile: 24 x 32 quads, 3/thread
        #pragma unroll
        for (int it = 0; it < 3; it++) {
            int i = tid + it * 256;
            int e = i >> 5;
            int q = i & 31;
            const float* wsrc = (e < E_) ? (Wa + (size_t)e * KDIM)
                                         : (Wi + (size_t)(e - E_) * KDIM);
            *(float4*)&S.t.W[e][q * 4] = *(const float4*)(wsrc + kc + q * 4);
        }
        __syncthreads();

        const int cb = ks * 16;  // this warp's 16-float window within the chunk
        #pragma unroll
        for (int kk = 0; kk < 4; kk++) {
            const int col = cb + kk * 4;
            ulonglong2 g0 = *(const ulonglong2*)&S.t.G[rg     ][col];
            ulonglong2 g1 = *(const ulonglong2*)&S.t.G[rg +  8][col];
            ulonglong2 g2 = *(const ulonglong2*)&S.t.G[rg + 16][col];
            ulonglong2 g3 = *(const ulonglong2*)&S.t.G[rg + 24][col];
            #pragma unroll
            for (int m = 0; m < 6; m++) {
                ulonglong2 w = *(const ulonglong2*)&S.t.W[eg + 4 * m][col];
                ffma2(acc[m][0], g0.x, w.x); ffma2(acc[m][0], g0.y, w.y);
                ffma2(acc[m][1], g1.x, w.x); ffma2(acc[m][1], g1.y, w.y);
                ffma2(acc[m][2], g2.x, w.x); ffma2(acc[m][2], g2.y, w.y);
                ffma2(acc[m][3], g3.x, w.x); ffma2(acc[m][3], g3.y, w.y);
            }
        }
        __syncthreads();   // also guards the Lp alias after the last chunk
    }

    // Deposit split-K partials (deterministic, no atomics)
    #pragma unroll
    for (int m = 0; m < 6; m++)
        #pragma unroll
        for (int i = 0; i < 4; i++) {
            float2 p = unpack2(acc[m][i]);
            S.Lp[ks][rg + 8 * i][eg + 4 * m] = p.x + p.y;
        }
    __syncthreads();

    // Reduce over the 8 K-slices in fixed order: 768 entries, 3/thread
    #pragma unroll
    for (int t = 0; t < 3; t++) {
        int idx = tid * 3 + t;
        int r = idx / NE;
        int e = idx - r * NE;
        float s = 0.f;
        #pragma unroll
        for (int k = 0; k < 8; k++) s += S.Lp[k][r][e];
        Ls[r][e] = s;
    }
    __syncthreads();

    // Gumbel-softmax straight-through per row (one thread per row)
    if (tid < ROWS) {
        int b = row0 + tid;
        if (b < B) {
            float* retA = out + (size_t)B * KDIM;
            float* retI = retA + (size_t)B * E_;
            #pragma unroll
            for (int gsel = 0; gsel < 2; gsel++) {
                const float* bias = gsel ? bi : ba;
                const float* gum  = gsel ? gi : ga;
                float* retp       = gsel ? retI : retA;
                float l[E_];
                float mx = -1e30f;
                #pragma unroll
                for (int e = 0; e < E_; e++) {
                    l[e] = Ls[tid][gsel * E_ + e] + bias[e] + gum[(size_t)b * E_ + e];
                    mx = fmaxf(mx, l[e]);
                }
                float s = 0.f;
                float y[E_];
                #pragma unroll
                for (int e = 0; e < E_; e++) { y[e] = expf(l[e] - mx); s += y[e]; }
                const float inv = 1.0f / s;
                float ys[E_];
                int   am = 0;
                float best = y[0] * inv;
                ys[0] = best;
                #pragma unroll
                for (int e = 1; e < E_; e++) {
                    ys[e] = y[e] * inv;
                    if (ys[e] > best) { best = ys[e]; am = e; }  // first-max (jnp.argmax)
                }
                #pragma unroll
                for (int e = 0; e < E_; e++) {
                    float h = (e == am) ? 1.0f : 0.0f;
                    retp[(size_t)b * E_ + e] = (h - ys[e]) + ys[e];  // exact ref arithmetic
                }
                g_scl[gsel * BMAX + b] = ((1.0f - ys[am]) + ys[am]) * (1.0f / 12.0f);
                g_idx[gsel * BMAX + b] = am;
            }
        }
    }
}

// ───────────── Kernel 2: gather selected expert rows, scale, store ─────────────
__global__ void __launch_bounds__(256) gate_gather_kernel(
    const float* __restrict__ audio, const float* __restrict__ image,
    float* __restrict__ out, int B)
{
    __shared__ float s_scl[2][R2];
    __shared__ int   s_idx[2][R2];

    const int tid  = threadIdx.x;
    const int row0 = blockIdx.x * R2;

    if (tid < 2 * R2) {
        int gsel = tid >> 3;       // R2 == 8
        int r    = tid & 7;
        int b    = row0 + r;
        if (b < B) {
            s_scl[gsel][r] = g_scl[gsel * BMAX + b];
            s_idx[gsel][r] = g_idx[gsel * BMAX + b];
        }
    }
    __syncthreads();

    const int V4 = KDIM / 4;  // 384 float4 per row
    #pragma unroll
    for (int j = 0; j < (R2 * V4) / 256; j++) {   // 12 iterations
        int i = tid + j * 256;
        int r = i / V4;
        int c = i - r * V4;
        int b = row0 + r;
        if (b >= B) continue;
        float4 v;
        float  s;
        if (c < (D_ / 4)) {
            v = *(const float4*)(audio + ((size_t)b * E_ + s_idx[0][r]) * D_ + c * 4);
            s = s_scl[0][r];
        } else {
            v = *(const float4*)(image + ((size_t)b * E_ + s_idx[1][r]) * D_ + (c - D_ / 4) * 4);
            s = s_scl[1][r];
        }
        v.x *= s; v.y *= s; v.z *= s; v.w *= s;
        *(float4*)(out + (size_t)b * KDIM + c * 4) = v;
    }
}

extern "C" void kernel_launch(void* const* d_in, const int* in_sizes, int n_in,
                              void* d_out, int out_size) {
    const float* audio = (const float*)d_in[0];
    const float* image = (const float*)d_in[1];
    const float* Wa    = (const float*)d_in[2];
    const float* ba    = (const float*)d_in[3];
    const float* Wi    = (const float*)d_in[4];
    const float* bi    = (const float*)d_in[5];
    const float* ga    = (const float*)d_in[6];
    const float* gi    = (const float*)d_in[7];
    float* out = (float*)d_out;

    const int B = in_sizes[0] / (E_ * D_);   // 16384

    const int grid1 = (B + ROWS - 1) / ROWS;  // 512
    gate_logits_kernel<<<grid1, 256>>>(audio, image, Wa, ba, Wi, bi, ga, gi, out, B);

    const int grid2 = (B + R2 - 1) / R2;      // 2048
    gate_gather_kernel<<<grid2, 256>>>(audio, image, out, B);
}